// round 14
// baseline (speedup 1.0000x reference)
#include <cuda_runtime.h>
#include <math.h>

// Problem constants
static constexpr int Bn = 8;
static constexpr int Cn = 256;
static constexpr int Nn = 4096;   // H*W = 64*64
static constexpr int Gn = 8;      // groups
static constexpr float EPSv = 1e-5f;

// Scratch (device globals — allocation-free per harness rules)
__device__ float g_xn[(size_t)Bn * Cn * Nn];                 // 32 MB
__device__ float g_q [(size_t)Bn * Cn * Nn];                 // 32 MB
__device__ float g_k [(size_t)Bn * Cn * Nn];                 // 32 MB
__device__ float g_v [(size_t)Bn * Cn * Nn];                 // 32 MB
__device__ float g_o [(size_t)Bn * Cn * Nn];                 // 32 MB
__device__ float g_s [(size_t)Bn * Nn * Nn];                 // 512 MB

// ---------------------------------------------------------------------------
// GroupNorm: one block per (b, g). Two passes over 32ch x 4096 = 128K floats.
// ---------------------------------------------------------------------------
__global__ void gn_kernel(const float* __restrict__ x,
                          const float* __restrict__ gamma,
                          const float* __restrict__ beta,
                          float* __restrict__ xn) {
    const int CPG = Cn / Gn;               // 32
    const int total = CPG * Nn;            // 131072
    int bg = blockIdx.x;
    int b = bg / Gn, g = bg % Gn;
    const float* xp = x + ((size_t)b * Cn + (size_t)g * CPG) * Nn;
    float*       op = xn + ((size_t)b * Cn + (size_t)g * CPG) * Nn;
    int tid = threadIdx.x;                 // blockDim = 512

    float s = 0.f, s2 = 0.f;
    for (int i = tid; i < total; i += 512) {
        float v = xp[i];
        s += v; s2 += v * v;
    }
    __shared__ float sh[512], sh2[512];
    sh[tid] = s; sh2[tid] = s2;
    __syncthreads();
    #pragma unroll
    for (int off = 256; off > 0; off >>= 1) {
        if (tid < off) { sh[tid] += sh[tid + off]; sh2[tid] += sh2[tid + off]; }
        __syncthreads();
    }
    float mu  = sh[0] * (1.0f / total);
    float var = sh2[0] * (1.0f / total) - mu * mu;
    float inv = rsqrtf(var + EPSv);

    for (int i = tid; i < total; i += 512) {
        int c = g * CPG + i / Nn;
        op[i] = (xp[i] - mu) * inv * gamma[c] + beta[c];
    }
}

// ---------------------------------------------------------------------------
// QKV GEMM: out[b][o][n] = sum_c W[o][c] * xn[b][c][n] + bias[o]
// M=256 (o), N=4096 (n), K=256 (c). 128x128 tile, BK=8, 256 thr, 8x8 micro.
// blockIdx.z encodes (b, which-of-qkv).
// ---------------------------------------------------------------------------
__global__ void __launch_bounds__(256) qkv_kernel(
        const float* __restrict__ xn,
        const float* __restrict__ wq, const float* __restrict__ bq,
        const float* __restrict__ wk, const float* __restrict__ bk,
        const float* __restrict__ wv, const float* __restrict__ bv) {
    int z = blockIdx.z;
    int b = z / 3, which = z % 3;
    const float* W    = (which == 0) ? wq : (which == 1) ? wk : wv;
    const float* bias = (which == 0) ? bq : (which == 1) ? bk : bv;
    float*       out  = (which == 0) ? g_q : (which == 1) ? g_k : g_v;

    int mBase = blockIdx.y * 128;   // output channel tile
    int nBase = blockIdx.x * 128;   // position tile

    __shared__ __align__(16) float As[8][128];
    __shared__ __align__(16) float Bs[8][128];

    int tid = threadIdx.x;
    int tx = tid & 15, ty = tid >> 4;
    int row0 = ty * 8, col0 = tx * 8;

    int am = tid >> 1;            // 0..127 (m for A-load)
    int ak = (tid & 1) * 4;       // 0 or 4
    int br = tid >> 5;            // 0..7 (k row for B-load)
    int bc = (tid & 31) * 4;      // 0..124

    const float* xb = xn + (size_t)b * Cn * Nn;

    float acc[8][8] = {};
    for (int k0 = 0; k0 < Cn; k0 += 8) {
        float4 w4 = *(const float4*)(W + (size_t)(mBase + am) * Cn + k0 + ak);
        float4 b4 = *(const float4*)(xb + (size_t)(k0 + br) * Nn + nBase + bc);
        As[ak + 0][am] = w4.x; As[ak + 1][am] = w4.y;
        As[ak + 2][am] = w4.z; As[ak + 3][am] = w4.w;
        *(float4*)(&Bs[br][bc]) = b4;
        __syncthreads();
        #pragma unroll
        for (int kk = 0; kk < 8; ++kk) {
            float a[8], bb[8];
            #pragma unroll
            for (int i = 0; i < 8; ++i) a[i]  = As[kk][row0 + i];
            #pragma unroll
            for (int j = 0; j < 8; ++j) bb[j] = Bs[kk][col0 + j];
            #pragma unroll
            for (int i = 0; i < 8; ++i)
                #pragma unroll
                for (int j = 0; j < 8; ++j)
                    acc[i][j] += a[i] * bb[j];
        }
        __syncthreads();
    }
    #pragma unroll
    for (int i = 0; i < 8; ++i) {
        int o = mBase + row0 + i;
        float bi = bias[o];
        float* dst = out + ((size_t)b * Cn + o) * Nn + nBase + col0;
        float4 o0 = make_float4(acc[i][0] + bi, acc[i][1] + bi, acc[i][2] + bi, acc[i][3] + bi);
        float4 o1 = make_float4(acc[i][4] + bi, acc[i][5] + bi, acc[i][6] + bi, acc[i][7] + bi);
        *(float4*)(dst)     = o0;
        *(float4*)(dst + 4) = o1;
    }
}

// ---------------------------------------------------------------------------
// Scores: S[b][i][j] = scale * sum_c q[b][c][i] * k[b][c][j]
// Both operands are k-major (c outer), i/j contiguous -> direct float4 tiles.
// ---------------------------------------------------------------------------
__global__ void __launch_bounds__(256) qkt_kernel(const float* __restrict__ q,
                                                  const float* __restrict__ kx,
                                                  float* __restrict__ s) {
    int b = blockIdx.z;
    int iBase = blockIdx.y * 128;
    int jBase = blockIdx.x * 128;

    __shared__ __align__(16) float As[8][128];
    __shared__ __align__(16) float Bs[8][128];

    int tid = threadIdx.x;
    int tx = tid & 15, ty = tid >> 4;
    int row0 = ty * 8, col0 = tx * 8;
    int lr = tid >> 5;            // 0..7
    int lc = (tid & 31) * 4;      // 0..124

    const float* qb = q  + (size_t)b * Cn * Nn;
    const float* kb = kx + (size_t)b * Cn * Nn;

    float acc[8][8] = {};
    for (int k0 = 0; k0 < Cn; k0 += 8) {
        float4 a4 = *(const float4*)(qb + (size_t)(k0 + lr) * Nn + iBase + lc);
        float4 b4 = *(const float4*)(kb + (size_t)(k0 + lr) * Nn + jBase + lc);
        *(float4*)(&As[lr][lc]) = a4;
        *(float4*)(&Bs[lr][lc]) = b4;
        __syncthreads();
        #pragma unroll
        for (int kk = 0; kk < 8; ++kk) {
            float a[8], bb[8];
            #pragma unroll
            for (int i = 0; i < 8; ++i) a[i]  = As[kk][row0 + i];
            #pragma unroll
            for (int j = 0; j < 8; ++j) bb[j] = Bs[kk][col0 + j];
            #pragma unroll
            for (int i = 0; i < 8; ++i)
                #pragma unroll
                for (int j = 0; j < 8; ++j)
                    acc[i][j] += a[i] * bb[j];
        }
        __syncthreads();
    }
    const float scale = 0.0625f;   // 1/sqrt(256)
    #pragma unroll
    for (int i = 0; i < 8; ++i) {
        float* dst = s + ((size_t)b * Nn + iBase + row0 + i) * Nn + jBase + col0;
        float4 o0 = make_float4(acc[i][0] * scale, acc[i][1] * scale,
                                acc[i][2] * scale, acc[i][3] * scale);
        float4 o1 = make_float4(acc[i][4] * scale, acc[i][5] * scale,
                                acc[i][6] * scale, acc[i][7] * scale);
        *(float4*)(dst)     = o0;
        *(float4*)(dst + 4) = o1;
    }
}

// ---------------------------------------------------------------------------
// Row softmax over 4096 elements. One block (256 thr) per row, 16 vals/thread.
// ---------------------------------------------------------------------------
__global__ void __launch_bounds__(256) softmax_kernel(float* __restrict__ s) {
    size_t row = blockIdx.x;                 // 0 .. B*N-1
    float* p = s + row * (size_t)Nn;
    int tid = threadIdx.x;

    float v[16];
    float m = -1e30f;
    #pragma unroll
    for (int i = 0; i < 16; ++i) { v[i] = p[tid + i * 256]; m = fmaxf(m, v[i]); }

    __shared__ float sh[256];
    sh[tid] = m; __syncthreads();
    #pragma unroll
    for (int off = 128; off > 0; off >>= 1) {
        if (tid < off) sh[tid] = fmaxf(sh[tid], sh[tid + off]);
        __syncthreads();
    }
    m = sh[0];
    __syncthreads();

    float sum = 0.f;
    #pragma unroll
    for (int i = 0; i < 16; ++i) { v[i] = __expf(v[i] - m); sum += v[i]; }
    sh[tid] = sum; __syncthreads();
    #pragma unroll
    for (int off = 128; off > 0; off >>= 1) {
        if (tid < off) sh[tid] += sh[tid + off];
        __syncthreads();
    }
    float inv = 1.0f / sh[0];
    #pragma unroll
    for (int i = 0; i < 16; ++i) p[tid + i * 256] = v[i] * inv;
}

// ---------------------------------------------------------------------------
// O = V * A^T : o[b][c][i] = sum_j v[b][c][j] * attn[b][i][j]
// M=256 (c), N=4096 (i), K=4096 (j). Both global loads contiguous in j.
// ---------------------------------------------------------------------------
__global__ void __launch_bounds__(256) av_kernel(const float* __restrict__ v,
                                                 const float* __restrict__ attn,
                                                 float* __restrict__ o) {
    int b = blockIdx.z;
    int mBase = blockIdx.y * 128;   // channel tile
    int nBase = blockIdx.x * 128;   // query-position tile

    __shared__ __align__(16) float As[8][128];
    __shared__ __align__(16) float Bs[8][128];

    int tid = threadIdx.x;
    int tx = tid & 15, ty = tid >> 4;
    int row0 = ty * 8, col0 = tx * 8;
    int am = tid >> 1;            // 0..127
    int ak = (tid & 1) * 4;       // 0 or 4

    const float* vb = v    + (size_t)b * Cn * Nn;
    const float* ab = attn + (size_t)b * Nn * Nn;

    float acc[8][8] = {};
    for (int k0 = 0; k0 < Nn; k0 += 8) {
        float4 v4 = *(const float4*)(vb + (size_t)(mBase + am) * Nn + k0 + ak);
        float4 a4 = *(const float4*)(ab + (size_t)(nBase + am) * Nn + k0 + ak);
        As[ak + 0][am] = v4.x; As[ak + 1][am] = v4.y;
        As[ak + 2][am] = v4.z; As[ak + 3][am] = v4.w;
        Bs[ak + 0][am] = a4.x; Bs[ak + 1][am] = a4.y;
        Bs[ak + 2][am] = a4.z; Bs[ak + 3][am] = a4.w;
        __syncthreads();
        #pragma unroll
        for (int kk = 0; kk < 8; ++kk) {
            float a[8], bb[8];
            #pragma unroll
            for (int i = 0; i < 8; ++i) a[i]  = As[kk][row0 + i];
            #pragma unroll
            for (int j = 0; j < 8; ++j) bb[j] = Bs[kk][col0 + j];
            #pragma unroll
            for (int i = 0; i < 8; ++i)
                #pragma unroll
                for (int j = 0; j < 8; ++j)
                    acc[i][j] += a[i] * bb[j];
        }
        __syncthreads();
    }
    #pragma unroll
    for (int i = 0; i < 8; ++i) {
        float* dst = o + ((size_t)b * Cn + mBase + row0 + i) * Nn + nBase + col0;
        float4 o0 = make_float4(acc[i][0], acc[i][1], acc[i][2], acc[i][3]);
        float4 o1 = make_float4(acc[i][4], acc[i][5], acc[i][6], acc[i][7]);
        *(float4*)(dst)     = o0;
        *(float4*)(dst + 4) = o1;
    }
}

// ---------------------------------------------------------------------------
// Proj + residual: out[b][o][n] = x[b][o][n] + sum_c wp[o][c]*gin[b][c][n] + bp[o]
// ---------------------------------------------------------------------------
__global__ void __launch_bounds__(256) proj_kernel(const float* __restrict__ gin,
                                                   const float* __restrict__ wp,
                                                   const float* __restrict__ bp,
                                                   const float* __restrict__ x,
                                                   float* __restrict__ out) {
    int b = blockIdx.z;
    int mBase = blockIdx.y * 128;
    int nBase = blockIdx.x * 128;

    __shared__ __align__(16) float As[8][128];
    __shared__ __align__(16) float Bs[8][128];

    int tid = threadIdx.x;
    int tx = tid & 15, ty = tid >> 4;
    int row0 = ty * 8, col0 = tx * 8;
    int am = tid >> 1;
    int ak = (tid & 1) * 4;
    int br = tid >> 5;
    int bc = (tid & 31) * 4;

    const float* gb = gin + (size_t)b * Cn * Nn;

    float acc[8][8] = {};
    for (int k0 = 0; k0 < Cn; k0 += 8) {
        float4 w4 = *(const float4*)(wp + (size_t)(mBase + am) * Cn + k0 + ak);
        float4 b4 = *(const float4*)(gb + (size_t)(k0 + br) * Nn + nBase + bc);
        As[ak + 0][am] = w4.x; As[ak + 1][am] = w4.y;
        As[ak + 2][am] = w4.z; As[ak + 3][am] = w4.w;
        *(float4*)(&Bs[br][bc]) = b4;
        __syncthreads();
        #pragma unroll
        for (int kk = 0; kk < 8; ++kk) {
            float a[8], bb[8];
            #pragma unroll
            for (int i = 0; i < 8; ++i) a[i]  = As[kk][row0 + i];
            #pragma unroll
            for (int j = 0; j < 8; ++j) bb[j] = Bs[kk][col0 + j];
            #pragma unroll
            for (int i = 0; i < 8; ++i)
                #pragma unroll
                for (int j = 0; j < 8; ++j)
                    acc[i][j] += a[i] * bb[j];
        }
        __syncthreads();
    }
    #pragma unroll
    for (int i = 0; i < 8; ++i) {
        int o = mBase + row0 + i;
        float bi = bp[o];
        size_t off = ((size_t)b * Cn + o) * Nn + nBase + col0;
        const float4 x0 = *(const float4*)(x + off);
        const float4 x1 = *(const float4*)(x + off + 4);
        float4 o0 = make_float4(acc[i][0] + bi + x0.x, acc[i][1] + bi + x0.y,
                                acc[i][2] + bi + x0.z, acc[i][3] + bi + x0.w);
        float4 o1 = make_float4(acc[i][4] + bi + x1.x, acc[i][5] + bi + x1.y,
                                acc[i][6] + bi + x1.z, acc[i][7] + bi + x1.w);
        *(float4*)(out + off)     = o0;
        *(float4*)(out + off + 4) = o1;
    }
}

// ---------------------------------------------------------------------------
extern "C" void kernel_launch(void* const* d_in, const int* in_sizes, int n_in,
                              void* d_out, int out_size) {
    const float* x     = (const float*)d_in[0];
    const float* gamma = (const float*)d_in[1];
    const float* beta  = (const float*)d_in[2];
    const float* wq    = (const float*)d_in[3];
    const float* bq    = (const float*)d_in[4];
    const float* wk    = (const float*)d_in[5];
    const float* bk    = (const float*)d_in[6];
    const float* wv    = (const float*)d_in[7];
    const float* bv    = (const float*)d_in[8];
    const float* wp    = (const float*)d_in[9];
    const float* bp    = (const float*)d_in[10];
    float* out = (float*)d_out;

    float *xn, *q, *k, *v, *o, *s;
    cudaGetSymbolAddress((void**)&xn, g_xn);
    cudaGetSymbolAddress((void**)&q,  g_q);
    cudaGetSymbolAddress((void**)&k,  g_k);
    cudaGetSymbolAddress((void**)&v,  g_v);
    cudaGetSymbolAddress((void**)&o,  g_o);
    cudaGetSymbolAddress((void**)&s,  g_s);

    // 1. GroupNorm
    gn_kernel<<<Bn * Gn, 512>>>(x, gamma, beta, xn);

    // 2. Q, K, V GEMMs (fused launch over z)
    {
        dim3 grid(Nn / 128, Cn / 128, Bn * 3);
        qkv_kernel<<<grid, 256>>>(xn, wq, bq, wk, bk, wv, bv);
    }

    // 3. S = scale * Q^T K
    {
        dim3 grid(Nn / 128, Nn / 128, Bn);
        qkt_kernel<<<grid, 256>>>(q, k, s);
    }

    // 4. row softmax
    softmax_kernel<<<Bn * Nn, 256>>>(s);

    // 5. O = V A^T
    {
        dim3 grid(Nn / 128, Cn / 128, Bn);
        av_kernel<<<grid, 256>>>(v, s, o);
    }

    // 6. proj + bias + residual
    {
        dim3 grid(Nn / 128, Cn / 128, Bn);
        proj_kernel<<<grid, 256>>>(o, wp, bp, x, out);
    }
}

// round 15
// speedup vs baseline: 1.0028x; 1.0028x over previous
#include <cuda_runtime.h>
#include <math.h>

// Problem constants
static constexpr int Bn = 8;
static constexpr int Cn = 256;
static constexpr int Nn = 4096;   // H*W = 64*64
static constexpr int Gn = 8;      // groups
static constexpr float EPSv = 1e-5f;

// Scratch (device globals — allocation-free per harness rules)
__device__ float g_xn[(size_t)Bn * Cn * Nn];                 // 32 MB
__device__ float g_q [(size_t)Bn * Cn * Nn];                 // 32 MB
__device__ float g_k [(size_t)Bn * Cn * Nn];                 // 32 MB
__device__ float g_v [(size_t)Bn * Cn * Nn];                 // 32 MB
__device__ float g_o [(size_t)Bn * Cn * Nn];                 // 32 MB
__device__ float g_s [(size_t)Bn * Nn * Nn];                 // 512 MB

// ---------------------------------------------------------------------------
// GroupNorm: one block per (b, g). Two passes over 32ch x 4096 = 128K floats.
// ---------------------------------------------------------------------------
__global__ void gn_kernel(const float* __restrict__ x,
                          const float* __restrict__ gamma,
                          const float* __restrict__ beta,
                          float* __restrict__ xn) {
    const int CPG = Cn / Gn;               // 32
    const int total = CPG * Nn;            // 131072
    int bg = blockIdx.x;
    int b = bg / Gn, g = bg % Gn;
    const float* xp = x + ((size_t)b * Cn + (size_t)g * CPG) * Nn;
    float*       op = xn + ((size_t)b * Cn + (size_t)g * CPG) * Nn;
    int tid = threadIdx.x;                 // blockDim = 512

    float s = 0.f, s2 = 0.f;
    for (int i = tid; i < total; i += 512) {
        float v = xp[i];
        s += v; s2 += v * v;
    }
    __shared__ float sh[512], sh2[512];
    sh[tid] = s; sh2[tid] = s2;
    __syncthreads();
    #pragma unroll
    for (int off = 256; off > 0; off >>= 1) {
        if (tid < off) { sh[tid] += sh[tid + off]; sh2[tid] += sh2[tid + off]; }
        __syncthreads();
    }
    float mu  = sh[0] * (1.0f / total);
    float var = sh2[0] * (1.0f / total) - mu * mu;
    float inv = rsqrtf(var + EPSv);

    for (int i = tid; i < total; i += 512) {
        int c = g * CPG + i / Nn;
        op[i] = (xp[i] - mu) * inv * gamma[c] + beta[c];
    }
}

// ---------------------------------------------------------------------------
// QKV GEMM: out[b][o][n] = sum_c W[o][c] * xn[b][c][n] + bias[o]
// M=256 (o), N=4096 (n), K=256 (c). 128x128 tile, BK=8, 256 thr, 8x8 micro.
// blockIdx.z encodes (b, which-of-qkv).
// ---------------------------------------------------------------------------
__global__ void __launch_bounds__(256) qkv_kernel(
        const float* __restrict__ xn,
        const float* __restrict__ wq, const float* __restrict__ bq,
        const float* __restrict__ wk, const float* __restrict__ bk,
        const float* __restrict__ wv, const float* __restrict__ bv) {
    int z = blockIdx.z;
    int b = z / 3, which = z % 3;
    const float* W    = (which == 0) ? wq : (which == 1) ? wk : wv;
    const float* bias = (which == 0) ? bq : (which == 1) ? bk : bv;
    float*       out  = (which == 0) ? g_q : (which == 1) ? g_k : g_v;

    int mBase = blockIdx.y * 128;   // output channel tile
    int nBase = blockIdx.x * 128;   // position tile

    __shared__ __align__(16) float As[8][128];
    __shared__ __align__(16) float Bs[8][128];

    int tid = threadIdx.x;
    int tx = tid & 15, ty = tid >> 4;
    int row0 = ty * 8, col0 = tx * 8;

    int am = tid >> 1;            // 0..127 (m for A-load)
    int ak = (tid & 1) * 4;       // 0 or 4
    int br = tid >> 5;            // 0..7 (k row for B-load)
    int bc = (tid & 31) * 4;      // 0..124

    const float* xb = xn + (size_t)b * Cn * Nn;

    float acc[8][8] = {};
    for (int k0 = 0; k0 < Cn; k0 += 8) {
        float4 w4 = *(const float4*)(W + (size_t)(mBase + am) * Cn + k0 + ak);
        float4 b4 = *(const float4*)(xb + (size_t)(k0 + br) * Nn + nBase + bc);
        As[ak + 0][am] = w4.x; As[ak + 1][am] = w4.y;
        As[ak + 2][am] = w4.z; As[ak + 3][am] = w4.w;
        *(float4*)(&Bs[br][bc]) = b4;
        __syncthreads();
        #pragma unroll
        for (int kk = 0; kk < 8; ++kk) {
            float a[8], bb[8];
            #pragma unroll
            for (int i = 0; i < 8; ++i) a[i]  = As[kk][row0 + i];
            #pragma unroll
            for (int j = 0; j < 8; ++j) bb[j] = Bs[kk][col0 + j];
            #pragma unroll
            for (int i = 0; i < 8; ++i)
                #pragma unroll
                for (int j = 0; j < 8; ++j)
                    acc[i][j] += a[i] * bb[j];
        }
        __syncthreads();
    }
    #pragma unroll
    for (int i = 0; i < 8; ++i) {
        int o = mBase + row0 + i;
        float bi = bias[o];
        float* dst = out + ((size_t)b * Cn + o) * Nn + nBase + col0;
        float4 o0 = make_float4(acc[i][0] + bi, acc[i][1] + bi, acc[i][2] + bi, acc[i][3] + bi);
        float4 o1 = make_float4(acc[i][4] + bi, acc[i][5] + bi, acc[i][6] + bi, acc[i][7] + bi);
        *(float4*)(dst)     = o0;
        *(float4*)(dst + 4) = o1;
    }
}

// ---------------------------------------------------------------------------
// Scores: S[b][i][j] = scale * sum_c q[b][c][i] * k[b][c][j]
// Both operands are k-major (c outer), i/j contiguous -> direct float4 tiles.
// ---------------------------------------------------------------------------
__global__ void __launch_bounds__(256) qkt_kernel(const float* __restrict__ q,
                                                  const float* __restrict__ kx,
                                                  float* __restrict__ s) {
    int b = blockIdx.z;
    int iBase = blockIdx.y * 128;
    int jBase = blockIdx.x * 128;

    __shared__ __align__(16) float As[8][128];
    __shared__ __align__(16) float Bs[8][128];

    int tid = threadIdx.x;
    int tx = tid & 15, ty = tid >> 4;
    int row0 = ty * 8, col0 = tx * 8;
    int lr = tid >> 5;            // 0..7
    int lc = (tid & 31) * 4;      // 0..124

    const float* qb = q  + (size_t)b * Cn * Nn;
    const float* kb = kx + (size_t)b * Cn * Nn;

    float acc[8][8] = {};
    for (int k0 = 0; k0 < Cn; k0 += 8) {
        float4 a4 = *(const float4*)(qb + (size_t)(k0 + lr) * Nn + iBase + lc);
        float4 b4 = *(const float4*)(kb + (size_t)(k0 + lr) * Nn + jBase + lc);
        *(float4*)(&As[lr][lc]) = a4;
        *(float4*)(&Bs[lr][lc]) = b4;
        __syncthreads();
        #pragma unroll
        for (int kk = 0; kk < 8; ++kk) {
            float a[8], bb[8];
            #pragma unroll
            for (int i = 0; i < 8; ++i) a[i]  = As[kk][row0 + i];
            #pragma unroll
            for (int j = 0; j < 8; ++j) bb[j] = Bs[kk][col0 + j];
            #pragma unroll
            for (int i = 0; i < 8; ++i)
                #pragma unroll
                for (int j = 0; j < 8; ++j)
                    acc[i][j] += a[i] * bb[j];
        }
        __syncthreads();
    }
    const float scale = 0.0625f;   // 1/sqrt(256)
    #pragma unroll
    for (int i = 0; i < 8; ++i) {
        float* dst = s + ((size_t)b * Nn + iBase + row0 + i) * Nn + jBase + col0;
        float4 o0 = make_float4(acc[i][0] * scale, acc[i][1] * scale,
                                acc[i][2] * scale, acc[i][3] * scale);
        float4 o1 = make_float4(acc[i][4] * scale, acc[i][5] * scale,
                                acc[i][6] * scale, acc[i][7] * scale);
        *(float4*)(dst)     = o0;
        *(float4*)(dst + 4) = o1;
    }
}

// ---------------------------------------------------------------------------
// Row softmax over 4096 elements. One block (256 thr) per row, 16 vals/thread.
// ---------------------------------------------------------------------------
__global__ void __launch_bounds__(256) softmax_kernel(float* __restrict__ s) {
    size_t row = blockIdx.x;                 // 0 .. B*N-1
    float* p = s + row * (size_t)Nn;
    int tid = threadIdx.x;

    float v[16];
    float m = -1e30f;
    #pragma unroll
    for (int i = 0; i < 16; ++i) { v[i] = p[tid + i * 256]; m = fmaxf(m, v[i]); }

    __shared__ float sh[256];
    sh[tid] = m; __syncthreads();
    #pragma unroll
    for (int off = 128; off > 0; off >>= 1) {
        if (tid < off) sh[tid] = fmaxf(sh[tid], sh[tid + off]);
        __syncthreads();
    }
    m = sh[0];
    __syncthreads();

    float sum = 0.f;
    #pragma unroll
    for (int i = 0; i < 16; ++i) { v[i] = __expf(v[i] - m); sum += v[i]; }
    sh[tid] = sum; __syncthreads();
    #pragma unroll
    for (int off = 128; off > 0; off >>= 1) {
        if (tid < off) sh[tid] += sh[tid + off];
        __syncthreads();
    }
    float inv = 1.0f / sh[0];
    #pragma unroll
    for (int i = 0; i < 16; ++i) p[tid + i * 256] = v[i] * inv;
}

// ---------------------------------------------------------------------------
// O = V * A^T : o[b][c][i] = sum_j v[b][c][j] * attn[b][i][j]
// M=256 (c), N=4096 (i), K=4096 (j). Both global loads contiguous in j.
// ---------------------------------------------------------------------------
__global__ void __launch_bounds__(256) av_kernel(const float* __restrict__ v,
                                                 const float* __restrict__ attn,
                                                 float* __restrict__ o) {
    int b = blockIdx.z;
    int mBase = blockIdx.y * 128;   // channel tile
    int nBase = blockIdx.x * 128;   // query-position tile

    __shared__ __align__(16) float As[8][128];
    __shared__ __align__(16) float Bs[8][128];

    int tid = threadIdx.x;
    int tx = tid & 15, ty = tid >> 4;
    int row0 = ty * 8, col0 = tx * 8;
    int am = tid >> 1;            // 0..127
    int ak = (tid & 1) * 4;       // 0 or 4

    const float* vb = v    + (size_t)b * Cn * Nn;
    const float* ab = attn + (size_t)b * Nn * Nn;

    float acc[8][8] = {};
    for (int k0 = 0; k0 < Nn; k0 += 8) {
        float4 v4 = *(const float4*)(vb + (size_t)(mBase + am) * Nn + k0 + ak);
        float4 a4 = *(const float4*)(ab + (size_t)(nBase + am) * Nn + k0 + ak);
        As[ak + 0][am] = v4.x; As[ak + 1][am] = v4.y;
        As[ak + 2][am] = v4.z; As[ak + 3][am] = v4.w;
        Bs[ak + 0][am] = a4.x; Bs[ak + 1][am] = a4.y;
        Bs[ak + 2][am] = a4.z; Bs[ak + 3][am] = a4.w;
        __syncthreads();
        #pragma unroll
        for (int kk = 0; kk < 8; ++kk) {
            float a[8], bb[8];
            #pragma unroll
            for (int i = 0; i < 8; ++i) a[i]  = As[kk][row0 + i];
            #pragma unroll
            for (int j = 0; j < 8; ++j) bb[j] = Bs[kk][col0 + j];
            #pragma unroll
            for (int i = 0; i < 8; ++i)
                #pragma unroll
                for (int j = 0; j < 8; ++j)
                    acc[i][j] += a[i] * bb[j];
        }
        __syncthreads();
    }
    #pragma unroll
    for (int i = 0; i < 8; ++i) {
        float* dst = o + ((size_t)b * Cn + mBase + row0 + i) * Nn + nBase + col0;
        float4 o0 = make_float4(acc[i][0], acc[i][1], acc[i][2], acc[i][3]);
        float4 o1 = make_float4(acc[i][4], acc[i][5], acc[i][6], acc[i][7]);
        *(float4*)(dst)     = o0;
        *(float4*)(dst + 4) = o1;
    }
}

// ---------------------------------------------------------------------------
// Proj + residual: out[b][o][n] = x[b][o][n] + sum_c wp[o][c]*gin[b][c][n] + bp[o]
// ---------------------------------------------------------------------------
__global__ void __launch_bounds__(256) proj_kernel(const float* __restrict__ gin,
                                                   const float* __restrict__ wp,
                                                   const float* __restrict__ bp,
                                                   const float* __restrict__ x,
                                                   float* __restrict__ out) {
    int b = blockIdx.z;
    int mBase = blockIdx.y * 128;
    int nBase = blockIdx.x * 128;

    __shared__ __align__(16) float As[8][128];
    __shared__ __align__(16) float Bs[8][128];

    int tid = threadIdx.x;
    int tx = tid & 15, ty = tid >> 4;
    int row0 = ty * 8, col0 = tx * 8;
    int am = tid >> 1;
    int ak = (tid & 1) * 4;
    int br = tid >> 5;
    int bc = (tid & 31) * 4;

    const float* gb = gin + (size_t)b * Cn * Nn;

    float acc[8][8] = {};
    for (int k0 = 0; k0 < Cn; k0 += 8) {
        float4 w4 = *(const float4*)(wp + (size_t)(mBase + am) * Cn + k0 + ak);
        float4 b4 = *(const float4*)(gb + (size_t)(k0 + br) * Nn + nBase + bc);
        As[ak + 0][am] = w4.x; As[ak + 1][am] = w4.y;
        As[ak + 2][am] = w4.z; As[ak + 3][am] = w4.w;
        *(float4*)(&Bs[br][bc]) = b4;
        __syncthreads();
        #pragma unroll
        for (int kk = 0; kk < 8; ++kk) {
            float a[8], bb[8];
            #pragma unroll
            for (int i = 0; i < 8; ++i) a[i]  = As[kk][row0 + i];
            #pragma unroll
            for (int j = 0; j < 8; ++j) bb[j] = Bs[kk][col0 + j];
            #pragma unroll
            for (int i = 0; i < 8; ++i)
                #pragma unroll
                for (int j = 0; j < 8; ++j)
                    acc[i][j] += a[i] * bb[j];
        }
        __syncthreads();
    }
    #pragma unroll
    for (int i = 0; i < 8; ++i) {
        int o = mBase + row0 + i;
        float bi = bp[o];
        size_t off = ((size_t)b * Cn + o) * Nn + nBase + col0;
        const float4 x0 = *(const float4*)(x + off);
        const float4 x1 = *(const float4*)(x + off + 4);
        float4 o0 = make_float4(acc[i][0] + bi + x0.x, acc[i][1] + bi + x0.y,
                                acc[i][2] + bi + x0.z, acc[i][3] + bi + x0.w);
        float4 o1 = make_float4(acc[i][4] + bi + x1.x, acc[i][5] + bi + x1.y,
                                acc[i][6] + bi + x1.z, acc[i][7] + bi + x1.w);
        *(float4*)(out + off)     = o0;
        *(float4*)(out + off + 4) = o1;
    }
}

// ---------------------------------------------------------------------------
extern "C" void kernel_launch(void* const* d_in, const int* in_sizes, int n_in,
                              void* d_out, int out_size) {
    const float* x     = (const float*)d_in[0];
    const float* gamma = (const float*)d_in[1];
    const float* beta  = (const float*)d_in[2];
    const float* wq    = (const float*)d_in[3];
    const float* bq    = (const float*)d_in[4];
    const float* wk    = (const float*)d_in[5];
    const float* bk    = (const float*)d_in[6];
    const float* wv    = (const float*)d_in[7];
    const float* bv    = (const float*)d_in[8];
    const float* wp    = (const float*)d_in[9];
    const float* bp    = (const float*)d_in[10];
    float* out = (float*)d_out;

    float *xn, *q, *k, *v, *o, *s;
    cudaGetSymbolAddress((void**)&xn, g_xn);
    cudaGetSymbolAddress((void**)&q,  g_q);
    cudaGetSymbolAddress((void**)&k,  g_k);
    cudaGetSymbolAddress((void**)&v,  g_v);
    cudaGetSymbolAddress((void**)&o,  g_o);
    cudaGetSymbolAddress((void**)&s,  g_s);

    // 1. GroupNorm
    gn_kernel<<<Bn * Gn, 512>>>(x, gamma, beta, xn);

    // 2. Q, K, V GEMMs (fused launch over z)
    {
        dim3 grid(Nn / 128, Cn / 128, Bn * 3);
        qkv_kernel<<<grid, 256>>>(xn, wq, bq, wk, bk, wv, bv);
    }

    // 3. S = scale * Q^T K
    {
        dim3 grid(Nn / 128, Nn / 128, Bn);
        qkt_kernel<<<grid, 256>>>(q, k, s);
    }

    // 4. row softmax
    softmax_kernel<<<Bn * Nn, 256>>>(s);

    // 5. O = V A^T
    {
        dim3 grid(Nn / 128, Cn / 128, Bn);
        av_kernel<<<grid, 256>>>(v, s, o);
    }

    // 6. proj + bias + residual
    {
        dim3 grid(Nn / 128, Cn / 128, Bn);
        proj_kernel<<<grid, 256>>>(o, wp, bp, x, out);
    }
}